// round 16
// baseline (speedup 1.0000x reference)
#include <cuda_runtime.h>
#include <cuda_fp16.h>
#include <cstdint>

#define NCHAN 64
#define NPTS  2048
#define DIN   256
#define DOUT  256

// ---------------------------------------------------------------------------
// helpers
// ---------------------------------------------------------------------------
__device__ __forceinline__ void cp16(uint32_t s, const void* g) {
    asm volatile("cp.async.cg.shared.global [%0], [%1], 16;"
                 :: "r"(s), "l"(g) : "memory");
}

__device__ __forceinline__ uint32_t smem_u32(const void* p) {
    uint32_t a;
    asm("{ .reg .u64 t; cvta.to.shared.u64 t, %1; cvt.u32.u64 %0, t; }"
        : "=r"(a) : "l"(p));
    return a;
}

// pack two f32 into f16x2 (lo, hi)
__device__ __forceinline__ uint32_t pack_h2(float lo, float hi) {
    uint32_t r;
    asm("cvt.rn.f16x2.f32 %0, %1, %2;" : "=r"(r) : "f"(hi), "f"(lo));
    return r;
}

__device__ __forceinline__ void mma_f16(float* c, const uint32_t* a, const uint32_t* b) {
    asm volatile(
        "mma.sync.aligned.m16n8k16.row.col.f32.f16.f16.f32 "
        "{%0,%1,%2,%3}, {%4,%5,%6,%7}, {%8,%9}, {%0,%1,%2,%3};"
        : "+f"(c[0]), "+f"(c[1]), "+f"(c[2]), "+f"(c[3])
        : "r"(a[0]), "r"(a[1]), "r"(a[2]), "r"(a[3]), "r"(b[0]), "r"(b[1]));
}

// ---------------------------------------------------------------------------
// single fused kernel: CTA 128x256x32, 256 threads, warps 2(m) x 4(n),
// warp 64x64, fp16 MMA. W gathered by model_idx and consumed DIRECTLY
// (k-major f32 in smem, f16-packed at fragment build) -- no pre-kernel.
// SMEM: [0..1024) bias (256 f32)
//       3 stages of { A 128 rows x 40 f32 (20480B),
//                     B  32 k-rows x 268 f32 (34304B) }
// ---------------------------------------------------------------------------
static constexpr int BM = 128, BN = 256, BK = 32;
static constexpr int ASTF = 40;                        // A stride in f32 (conflict-free)
static constexpr int BSTF = 268;                       // B k-row stride in f32 (conflict-free)
static constexpr int A_STAGE = BM * ASTF * 4;          // 20480
static constexpr int B_STAGE = BK * BSTF * 4;          // 34304
static constexpr int STAGE_BYTES = A_STAGE + B_STAGE;  // 54784
static constexpr int SMEM_BYTES = 1024 + 3 * STAGE_BYTES;  // 165376

__global__ void __launch_bounds__(256, 1)
adaptive_linear_gemm(const float* __restrict__ x, const float* __restrict__ tvec,
                     const int* __restrict__ midx,
                     const float* __restrict__ W,
                     const float* __restrict__ Bmat, float* __restrict__ out) {
    extern __shared__ char smem[];
    const uint32_t sb = smem_u32(smem);
    const int tid = threadIdx.x;
    const int c   = blockIdx.y;
    const int m0  = blockIdx.x * BM;

    const int wid = tid >> 5, lane = tid & 31;
    const int wm = wid & 1, wn = wid >> 1;   // warp tile origin (wm*64, wn*64)
    const int g = lane >> 2, t = lane & 3;

    // bias gather into SMEM
    {
        const int bidx = (int)(tvec[c] * 31.0f);
        float* sbias = (float*)smem;
        sbias[tid] = Bmat[bidx * DOUT + tid];
    }

    const float* xc = x + ((size_t)c * NPTS + m0) * DIN;
    const float* wc = W + (size_t)midx[c] * DIN * DOUT;   // gathered, k-major [k][n]

    // async stage loader: K-chunk ks (32 rows) into buffer buf
    auto load_stage = [&](int buf, int ks) {
        const uint32_t a_base = sb + 1024 + buf * STAGE_BYTES;
        const uint32_t b_base = a_base + A_STAGE;
        // A: 128 rows x 32 f32 = 1024 16B chunks (8/row), 4 per thread
#pragma unroll
        for (int i = 0; i < 4; i++) {
            int ch = tid + i * 256;
            int row = ch >> 3, seg = ch & 7;
            cp16(a_base + (uint32_t)(row * (ASTF * 4) + seg * 16),
                 xc + (size_t)row * DIN + ks * BK + seg * 4);
        }
        // B: 32 k-rows x 256 f32 = 2048 16B chunks (64/row), 8 per thread
#pragma unroll
        for (int i = 0; i < 8; i++) {
            int ch = tid + i * 256;
            int row = ch >> 6, seg = ch & 63;
            cp16(b_base + (uint32_t)(row * (BSTF * 4) + seg * 16),
                 wc + (size_t)(ks * BK + row) * DOUT + seg * 4);
        }
        asm volatile("cp.async.commit_group;" ::: "memory");
    };

    float acc[4][8][4];
#pragma unroll
    for (int mi = 0; mi < 4; mi++)
#pragma unroll
        for (int ni = 0; ni < 8; ni++)
#pragma unroll
            for (int j = 0; j < 4; j++) acc[mi][ni][j] = 0.0f;

    uint32_t afr[2][16], bfr[2][16];

    // prologue: stages 0 and 1
    load_stage(0, 0);
    load_stage(1, 1);

#pragma unroll 1
    for (int ks = 0; ks < 8; ++ks) {
        if (ks < 7) asm volatile("cp.async.wait_group 1;" ::: "memory");
        else        asm volatile("cp.async.wait_group 0;" ::: "memory");
        __syncthreads();
        if (ks + 2 < 8) load_stage((ks + 2) % 3, ks + 2);

        const int buf = ks % 3;
        const float* As = (const float*)(smem + 1024 + buf * STAGE_BYTES);
        const float* Bs = (const float*)(smem + 1024 + buf * STAGE_BYTES + A_STAGE);

        auto load_frags = [&](int kk, int p) {
            // A fragments: rows m, k-contiguous (row-major) -> float2 + pack
#pragma unroll
            for (int mi = 0; mi < 4; mi++) {
                const int r = wm * 64 + mi * 16 + g;
                const float2* Ar0 = (const float2*)(As + r * ASTF) + kk * 8;
                const float2* Ar1 = (const float2*)(As + (r + 8) * ASTF) + kk * 8;
                float2 v0 = Ar0[t], v1 = Ar1[t], v2 = Ar0[t + 4], v3 = Ar1[t + 4];
                afr[p][mi * 4 + 0] = pack_h2(v0.x, v0.y);
                afr[p][mi * 4 + 1] = pack_h2(v1.x, v1.y);
                afr[p][mi * 4 + 2] = pack_h2(v2.x, v2.y);
                afr[p][mi * 4 + 3] = pack_h2(v3.x, v3.y);
            }
            // B fragments from k-major tile: B[k][n]; col-major operand needs
            // {B[2t][n],B[2t+1][n]} and {B[2t+8][n],B[2t+9][n]}
            const int k0 = kk * 16 + 2 * t;
#pragma unroll
            for (int ni = 0; ni < 8; ni++) {
                const int rn = wn * 64 + ni * 8 + g;
                const float* Bk = Bs + k0 * BSTF + rn;
                bfr[p][ni * 2 + 0] = pack_h2(Bk[0],        Bk[BSTF]);
                bfr[p][ni * 2 + 1] = pack_h2(Bk[8 * BSTF], Bk[9 * BSTF]);
            }
        };

        load_frags(0, 0);
#pragma unroll
        for (int kk = 0; kk < 2; kk++) {   // two k16 sub-steps per BK=32
            if (kk < 1) load_frags(kk + 1, (kk + 1) & 1);
            const int p = kk & 1;
#pragma unroll
            for (int mi = 0; mi < 4; mi++)
#pragma unroll
                for (int ni = 0; ni < 8; ni++)
                    mma_f16(acc[mi][ni], &afr[p][mi * 4], &bfr[p][ni * 2]);
        }
    }

    // epilogue: accumulators + bias -> gmem (float2 stores)
    {
        const float* sbias = (const float*)smem;
        float* op = out + ((size_t)c * NPTS + m0) * DOUT;
#pragma unroll
        for (int mi = 0; mi < 4; mi++) {
            const int r0 = wm * 64 + mi * 16 + g;
#pragma unroll
            for (int ni = 0; ni < 8; ni++) {
                const int col = wn * 64 + ni * 8 + 2 * t;
                const float b0 = sbias[col], b1 = sbias[col + 1];
                float2 v0 = {acc[mi][ni][0] + b0, acc[mi][ni][1] + b1};
                float2 v1 = {acc[mi][ni][2] + b0, acc[mi][ni][3] + b1};
                *(float2*)(op + (size_t)r0 * DOUT + col) = v0;
                *(float2*)(op + (size_t)(r0 + 8) * DOUT + col) = v1;
            }
        }
    }
}

// ---------------------------------------------------------------------------
// launcher -- single kernel, no pre-pass
// ---------------------------------------------------------------------------
extern "C" void kernel_launch(void* const* d_in, const int* in_sizes, int n_in,
                              void* d_out, int out_size) {
    const float* x    = (const float*)d_in[0];
    const float* tvec = (const float*)d_in[1];
    const int*   midx = (const int*)d_in[2];
    const float* W    = (const float*)d_in[3];
    const float* Bm   = (const float*)d_in[4];
    float* out = (float*)d_out;

    cudaFuncSetAttribute(adaptive_linear_gemm,
                         cudaFuncAttributeMaxDynamicSharedMemorySize, SMEM_BYTES);

    adaptive_linear_gemm<<<dim3(NPTS / BM, NCHAN), 256, SMEM_BYTES>>>(
        x, tvec, midx, W, Bm, out);
}

// round 17
// speedup vs baseline: 1.1025x; 1.1025x over previous
#include <cuda_runtime.h>
#include <cuda_fp16.h>
#include <cstdint>

#define NCHAN 64
#define NPTS  2048
#define DIN   256
#define DOUT  256

// 8 MB scratch: per-MODEL transposed (n-major) fp16 weights, Wt[m][n][k]
__device__ __half g_Wt[NCHAN * DIN * DOUT];
__device__ int    g_used[NCHAN];

// ---------------------------------------------------------------------------
// helpers
// ---------------------------------------------------------------------------
__device__ __forceinline__ void cp16(uint32_t s, const void* g) {
    asm volatile("cp.async.cg.shared.global [%0], [%1], 16;"
                 :: "r"(s), "l"(g) : "memory");
}

__device__ __forceinline__ uint32_t smem_u32(const void* p) {
    uint32_t a;
    asm("{ .reg .u64 t; cvta.to.shared.u64 t, %1; cvt.u32.u64 %0, t; }"
        : "=r"(a) : "l"(p));
    return a;
}

// pack two f32 into f16x2 (lo, hi)
__device__ __forceinline__ uint32_t pack_h2(float lo, float hi) {
    uint32_t r;
    asm("cvt.rn.f16x2.f32 %0, %1, %2;" : "=r"(r) : "f"(hi), "f"(lo));
    return r;
}

__device__ __forceinline__ void mma_f16(float* c, const uint32_t* a, const uint32_t* b) {
    asm volatile(
        "mma.sync.aligned.m16n8k16.row.col.f32.f16.f16.f32 "
        "{%0,%1,%2,%3}, {%4,%5,%6,%7}, {%8,%9}, {%0,%1,%2,%3};"
        : "+f"(c[0]), "+f"(c[1]), "+f"(c[2]), "+f"(c[3])
        : "r"(a[0]), "r"(a[1]), "r"(a[2]), "r"(a[3]), "r"(b[0]), "r"(b[1]));
}

// ---------------------------------------------------------------------------
// pre-pass A: mark used models (and clear stale flags deterministically)
// ---------------------------------------------------------------------------
__global__ void mark_used_kernel(const int* __restrict__ midx) {
    const int i = threadIdx.x;           // 64 threads
    g_used[i] = 0;
    __syncthreads();
    atomicExch(&g_used[midx[i]], 1);
}

// ---------------------------------------------------------------------------
// pre-pass B: transpose W[m] (k-major) -> Wt[m] (n-major fp16), used models only
// ---------------------------------------------------------------------------
__global__ void transpose_kernel(const float* __restrict__ W) {
    const int m = blockIdx.z;
    if (!g_used[m]) return;
    __shared__ float tile[32][33];
    const int kb = blockIdx.x * 32;
    const int nb = blockIdx.y * 32;
    const int tx = threadIdx.x, ty = threadIdx.y;  // (32, 8)

#pragma unroll
    for (int j = 0; j < 32; j += 8)
        tile[ty + j][tx] = W[((size_t)m * DIN + kb + ty + j) * DOUT + nb + tx];
    __syncthreads();
#pragma unroll
    for (int j = 0; j < 32; j += 8) {
        float v = tile[tx][ty + j];
        g_Wt[((size_t)m * DOUT + nb + ty + j) * DIN + kb + tx] = __float2half_rn(v);
    }
}

// ---------------------------------------------------------------------------
// main GEMM (R6, unchanged): CTA 128x256x64, 256 threads, warps 2(m) x 4(n),
// warp 64x64, fp16 MMA.
// SMEM: [0..1024) bias, then 3 stages of {A 128x(72 f32), B 256x(72 f16)}
// ---------------------------------------------------------------------------
static constexpr int BM = 128, BN = 256, BK = 64;
static constexpr int ASTF = 72;                       // A stride in f32
static constexpr int BSTH = 72;                       // B stride in f16
static constexpr int A_BYTES = BM * ASTF * 4;         // 36864
static constexpr int B_BYTES = BN * BSTH * 2;         // 36864
static constexpr int STAGE_BYTES = A_BYTES + B_BYTES; // 73728
static constexpr int SMEM_BYTES = 1024 + 3 * STAGE_BYTES;  // 222208

__global__ void __launch_bounds__(256, 1)
adaptive_linear_gemm(const float* __restrict__ x, const float* __restrict__ tvec,
                     const int* __restrict__ midx,
                     const float* __restrict__ Bmat, float* __restrict__ out) {
    extern __shared__ char smem[];
    const uint32_t sb = smem_u32(smem);
    const int tid = threadIdx.x;
    const int c   = blockIdx.y;
    const int m0  = blockIdx.x * BM;

    const int wid = tid >> 5, lane = tid & 31;
    const int wm = wid & 1, wn = wid >> 1;   // warp tile origin (wm*64, wn*64)
    const int g = lane >> 2, t = lane & 3;

    // bias gather into SMEM
    {
        const int bidx = (int)(tvec[c] * 31.0f);
        float* sbias = (float*)smem;
        sbias[tid] = Bmat[bidx * DOUT + tid];
    }

    const float*  xc = x + ((size_t)c * NPTS + m0) * DIN;
    const __half* wc = g_Wt + (size_t)midx[c] * DIN * DOUT;   // per-model Wt

    // async stage loader: chunk ks (64 K-columns) into buffer buf
    auto load_stage = [&](int buf, int ks) {
        const uint32_t a_base = sb + 1024 + buf * STAGE_BYTES;
        const uint32_t b_base = a_base + A_BYTES;
        // A: 128 rows x 64 f32 = 2048 16B chunks (16/row), 8 per thread
#pragma unroll
        for (int i = 0; i < 8; i++) {
            int ch = tid + i * 256;
            int row = ch >> 4, seg = ch & 15;
            cp16(a_base + (uint32_t)(row * (ASTF * 4) + seg * 16),
                 xc + (size_t)row * DIN + ks * BK + seg * 4);
        }
        // B: 256 rows x 64 f16 = 2048 16B chunks (8/row), 8 per thread
#pragma unroll
        for (int i = 0; i < 8; i++) {
            int ch = tid + i * 256;
            int row = ch >> 3, seg = ch & 7;
            cp16(b_base + (uint32_t)(row * (BSTH * 2) + seg * 16),
                 wc + (size_t)row * DIN + ks * BK + seg * 8);
        }
        asm volatile("cp.async.commit_group;" ::: "memory");
    };

    float acc[4][8][4];
#pragma unroll
    for (int mi = 0; mi < 4; mi++)
#pragma unroll
        for (int ni = 0; ni < 8; ni++)
#pragma unroll
            for (int j = 0; j < 4; j++) acc[mi][ni][j] = 0.0f;

    // fragment double buffers (pre-packed f16x2)
    uint32_t afr[2][16], bfr[2][16];

    // prologue: load stages 0 and 1
    load_stage(0, 0);
    load_stage(1, 1);

#pragma unroll 1
    for (int ks = 0; ks < 4; ++ks) {
        if (ks < 3) asm volatile("cp.async.wait_group 1;" ::: "memory");
        else        asm volatile("cp.async.wait_group 0;" ::: "memory");
        __syncthreads();
        if (ks + 2 < 4) load_stage((ks + 2) % 3, ks + 2);

        const float*  As = (const float*)(smem + 1024 + (ks % 3) * STAGE_BYTES);
        const __half* Bs = (const __half*)(smem + 1024 + (ks % 3) * STAGE_BYTES + A_BYTES);

        auto load_frags = [&](int kk, int p) {
#pragma unroll
            for (int mi = 0; mi < 4; mi++) {
                const int r = wm * 64 + mi * 16 + g;
                const float2* Ar0 = (const float2*)(As + r * ASTF) + kk * 8;
                const float2* Ar1 = (const float2*)(As + (r + 8) * ASTF) + kk * 8;
                float2 v0 = Ar0[t], v1 = Ar1[t], v2 = Ar0[t + 4], v3 = Ar1[t + 4];
                afr[p][mi * 4 + 0] = pack_h2(v0.x, v0.y);
                afr[p][mi * 4 + 1] = pack_h2(v1.x, v1.y);
                afr[p][mi * 4 + 2] = pack_h2(v2.x, v2.y);
                afr[p][mi * 4 + 3] = pack_h2(v3.x, v3.y);
            }
#pragma unroll
            for (int ni = 0; ni < 8; ni++) {
                const int rn = wn * 64 + ni * 8 + g;
                const uint32_t* Br = (const uint32_t*)(Bs + rn * BSTH + kk * 16);
                bfr[p][ni * 2 + 0] = Br[t];
                bfr[p][ni * 2 + 1] = Br[t + 4];
            }
        };

        load_frags(0, 0);
#pragma unroll
        for (int kk = 0; kk < 4; kk++) {   // four k16 sub-steps per BK=64
            if (kk < 3) load_frags(kk + 1, (kk + 1) & 1);
            const int p = kk & 1;
#pragma unroll
            for (int mi = 0; mi < 4; mi++)
#pragma unroll
                for (int ni = 0; ni < 8; ni++)
                    mma_f16(acc[mi][ni], &afr[p][mi * 4], &bfr[p][ni * 2]);
        }
    }

    // epilogue: accumulators + bias -> gmem (float2 stores)
    {
        const float* sbias = (const float*)smem;
        float* op = out + ((size_t)c * NPTS + m0) * DOUT;
#pragma unroll
        for (int mi = 0; mi < 4; mi++) {
            const int r0 = wm * 64 + mi * 16 + g;
#pragma unroll
            for (int ni = 0; ni < 8; ni++) {
                const int col = wn * 64 + ni * 8 + 2 * t;
                const float b0 = sbias[col], b1 = sbias[col + 1];
                float2 v0 = {acc[mi][ni][0] + b0, acc[mi][ni][1] + b1};
                float2 v1 = {acc[mi][ni][2] + b0, acc[mi][ni][3] + b1};
                *(float2*)(op + (size_t)r0 * DOUT + col) = v0;
                *(float2*)(op + (size_t)(r0 + 8) * DOUT + col) = v1;
            }
        }
    }
}

// ---------------------------------------------------------------------------
// launcher
// ---------------------------------------------------------------------------
extern "C" void kernel_launch(void* const* d_in, const int* in_sizes, int n_in,
                              void* d_out, int out_size) {
    const float* x    = (const float*)d_in[0];
    const float* tvec = (const float*)d_in[1];
    const int*   midx = (const int*)d_in[2];
    const float* W    = (const float*)d_in[3];
    const float* Bm   = (const float*)d_in[4];
    float* out = (float*)d_out;

    cudaFuncSetAttribute(adaptive_linear_gemm,
                         cudaFuncAttributeMaxDynamicSharedMemorySize, SMEM_BYTES);

    mark_used_kernel<<<1, NCHAN>>>(midx);
    transpose_kernel<<<dim3(8, 8, NCHAN), dim3(32, 8)>>>(W);
    adaptive_linear_gemm<<<dim3(NPTS / BM, NCHAN), 256, SMEM_BYTES>>>(
        x, tvec, midx, Bm, out);
}